// round 4
// baseline (speedup 1.0000x reference)
#include <cuda_runtime.h>
#include <cstdint>

// YoloLayer: x (64, 30, 152, 152) f32 -> out (64, 3*152*152, 10) f32
// VEC=2, per-warp smem staging (no block barrier), launch_bounds(256,8).

#define G     152
#define GG    (G * G)            // 23104, even
#define A     3
#define F     10
#define B     64
#define BLK   256
#define VEC   2
#define POS_PER_BLK (BLK * VEC)  // 512
#define WARP_FLOATS (32 * VEC * F)  // 640 floats per warp slice

__constant__ float c_anchor_w[A] = {12.0f, 19.0f, 40.0f};
__constant__ float c_anchor_h[A] = {16.0f, 36.0f, 28.0f};

__device__ __forceinline__ float fsigmoid(float v) {
    return 1.0f / (1.0f + __expf(-v));
}

__global__ void __launch_bounds__(BLK, 8) yolo_kernel(
    const float* __restrict__ x,
    const int*   __restrict__ img,
    float*       __restrict__ out)
{
    __shared__ float s[POS_PER_BLK * F];     // 20480 B

    const int tid  = threadIdx.x;
    const int wid  = tid >> 5;
    const int lane = tid & 31;
    const int p0   = (blockIdx.x * BLK + tid) * VEC;   // even position

    int iv = img[0];
    float img_f = (iv > 0 && iv < 1000000) ? (float)iv : __int_as_float(iv);
    const float stride = img_f / (float)G;             // 8.0

    // Both positions share b, a, yy (G even)
    const int b    = p0 / (A * GG);
    int rem        = p0 - b * (A * GG);
    const int a    = rem / GG;
    const int sidx = rem - a * GG;
    const int yy   = sidx / G;
    const int xx0  = sidx - yy * G;

    const float* base = x + ((size_t)(b * (A * F) + a * F)) * GG + sidx;

    // 10 independent LDG.64
    float2 v[F];
#pragma unroll
    for (int f = 0; f < F; f++)
        v[f] = *(const float2*)(base + (size_t)f * GG);

    const float SXY = 1.05f;
    const float OFF = 0.025f;
    const float aw  = c_anchor_w[a];
    const float ah  = c_anchor_h[a];
    const float fy  = (float)yy;

    float* ws = s + wid * WARP_FLOATS;       // this warp's 640-float region
    float* sp = ws + lane * (VEC * F);
#pragma unroll
    for (int j = 0; j < VEC; j++) {
        float r0 = (fsigmoid(j ? v[0].y : v[0].x) * SXY - OFF + (float)(xx0 + j)) * stride;
        float r1 = (fsigmoid(j ? v[1].y : v[1].x) * SXY - OFF + fy) * stride;
        float r2 = __expf(j ? v[2].y : v[2].x) * aw;
        float r3 = __expf(j ? v[3].y : v[3].x) * ah;
        ((float4*)(sp + j * F))[0] = make_float4(r0, r1, r2, r3);
        float r4 = j ? v[4].y : v[4].x;
        float r5 = j ? v[5].y : v[5].x;
        float r6 = fsigmoid(j ? v[6].y : v[6].x);
        float r7 = fsigmoid(j ? v[7].y : v[7].x);
        ((float4*)(sp + j * F))[1] = make_float4(r4, r5, r6, r7);
        float r8 = fsigmoid(j ? v[8].y : v[8].x);
        float r9 = fsigmoid(j ? v[9].y : v[9].x);
        ((float2*)(sp + j * F))[4] = make_float2(r8, r9);
    }

    __syncwarp();

    // Warp output slice: 640 contiguous floats = 160 float4.
    // 5 fully-coalesced STG.128 per lane. No block barrier anywhere.
    float4* ob = (float4*)(out + ((size_t)blockIdx.x * BLK + wid * 32) * (VEC * F));
    const float4* sf = (const float4*)ws;
#pragma unroll
    for (int jj = 0; jj < 5; jj++)
        ob[lane + jj * 32] = sf[lane + jj * 32];
}

extern "C" void kernel_launch(void* const* d_in, const int* in_sizes, int n_in,
                              void* d_out, int out_size)
{
    const float* x   = (const float*)d_in[0];
    const int*   img = (n_in >= 2) ? (const int*)d_in[1] : nullptr;
    float*       out = (float*)d_out;

    const int total = B * A * GG;             // 4,435,968
    const int grid  = total / POS_PER_BLK;    // 8664 exactly

    yolo_kernel<<<grid, BLK>>>(x, img, out);
}

// round 6
// speedup vs baseline: 1.0303x; 1.0303x over previous
#include <cuda_runtime.h>
#include <cstdint>

// YoloLayer: x (64, 30, 152, 152) f32 -> out (64, 3*152*152, 10) f32
// VEC=2 (LDG.64 streaming loads), per-warp smem staging + __syncwarp,
// natural register allocation (no occupancy clamp), STG.128 output.

#define G     152
#define GG    (G * G)            // 23104, even
#define A     3
#define F     10
#define B     64
#define BLK   256
#define VEC   2
#define POS_PER_BLK (BLK * VEC)     // 512
#define WARP_FLOATS (32 * VEC * F)  // 640 floats per warp slice

__constant__ float c_anchor_w[A] = {12.0f, 19.0f, 40.0f};
__constant__ float c_anchor_h[A] = {16.0f, 36.0f, 28.0f};

__device__ __forceinline__ float fsigmoid(float v) {
    return 1.0f / (1.0f + __expf(-v));
}

__global__ void __launch_bounds__(BLK) yolo_kernel(
    const float* __restrict__ x,
    const int*   __restrict__ img,
    float*       __restrict__ out)
{
    __shared__ float s[POS_PER_BLK * F];     // 20480 B

    const int tid  = threadIdx.x;
    const int wid  = tid >> 5;
    const int lane = tid & 31;
    const int p0   = (blockIdx.x * BLK + tid) * VEC;   // even position

    int iv = img[0];
    float img_f = (iv > 0 && iv < 1000000) ? (float)iv : __int_as_float(iv);
    const float stride = img_f / (float)G;             // 8.0

    // Both positions share b, a, yy (G even)
    const int b    = p0 / (A * GG);
    int rem        = p0 - b * (A * GG);
    const int a    = rem / GG;
    const int sidx = rem - a * GG;
    const int yy   = sidx / G;
    const int xx0  = sidx - yy * G;

    const float* base = x + ((size_t)(b * (A * F) + a * F)) * GG + sidx;

    // 10 independent streaming LDG.64 (read-once data, evict-first)
    float2 v[F];
#pragma unroll
    for (int f = 0; f < F; f++)
        v[f] = __ldcs((const float2*)(base + (size_t)f * GG));

    const float SXY = 1.05f;
    const float OFF = 0.025f;
    const float aw  = c_anchor_w[a];
    const float ah  = c_anchor_h[a];
    const float fy  = (float)yy;

    float* ws = s + wid * WARP_FLOATS;       // this warp's 640-float region
    float* sp = ws + lane * (VEC * F);
#pragma unroll
    for (int j = 0; j < VEC; j++) {
        float r0 = (fsigmoid(j ? v[0].y : v[0].x) * SXY - OFF + (float)(xx0 + j)) * stride;
        float r1 = (fsigmoid(j ? v[1].y : v[1].x) * SXY - OFF + fy) * stride;
        float r2 = __expf(j ? v[2].y : v[2].x) * aw;
        float r3 = __expf(j ? v[3].y : v[3].x) * ah;
        ((float4*)(sp + j * F))[0] = make_float4(r0, r1, r2, r3);
        float r4 = j ? v[4].y : v[4].x;
        float r5 = j ? v[5].y : v[5].x;
        float r6 = fsigmoid(j ? v[6].y : v[6].x);
        float r7 = fsigmoid(j ? v[7].y : v[7].x);
        ((float4*)(sp + j * F))[1] = make_float4(r4, r5, r6, r7);
        float r8 = fsigmoid(j ? v[8].y : v[8].x);
        float r9 = fsigmoid(j ? v[9].y : v[9].x);
        ((float2*)(sp + j * F))[4] = make_float2(r8, r9);
    }

    __syncwarp();

    // Warp output slice: 640 contiguous floats = 160 float4.
    // 5 fully-coalesced STG.128 per lane. No block barrier.
    float4* ob = (float4*)(out + ((size_t)blockIdx.x * BLK + wid * 32) * (VEC * F));
    const float4* sf = (const float4*)ws;
#pragma unroll
    for (int jj = 0; jj < 5; jj++)
        ob[lane + jj * 32] = sf[lane + jj * 32];
}

extern "C" void kernel_launch(void* const* d_in, const int* in_sizes, int n_in,
                              void* d_out, int out_size)
{
    const float* x   = (const float*)d_in[0];
    const int*   img = (n_in >= 2) ? (const int*)d_in[1] : nullptr;
    float*       out = (float*)d_out;

    const int total = B * A * GG;             // 4,435,968
    const int grid  = total / POS_PER_BLK;    // 8664 exactly

    yolo_kernel<<<grid, BLK>>>(x, img, out);
}

// round 8
// speedup vs baseline: 1.0494x; 1.0185x over previous
#include <cuda_runtime.h>
#include <cstdint>

// YoloLayer: x (64, 30, 152, 152) f32 -> out (64, 3*152*152, 10) f32
// R3 structure (best measured): VEC=2 LDG.64 loads, 20KB block smem staging,
// STG.128 coalesced output. Added: streaming cache hints on both sides
// (__ldcs / __stcs) to keep L2 free for write-combining.

#define G     152
#define GG    (G * G)            // 23104, even
#define A     3
#define F     10
#define B     64
#define BLK   256
#define VEC   2
#define POS_PER_BLK (BLK * VEC)  // 512

__constant__ float c_anchor_w[A] = {12.0f, 19.0f, 40.0f};
__constant__ float c_anchor_h[A] = {16.0f, 36.0f, 28.0f};

__device__ __forceinline__ float fsigmoid(float v) {
    return 1.0f / (1.0f + __expf(-v));
}

__global__ __launch_bounds__(BLK) void yolo_kernel(
    const float* __restrict__ x,
    const int*   __restrict__ img,
    float*       __restrict__ out)
{
    __shared__ float s[POS_PER_BLK * F];     // 20480 B

    const int tid = threadIdx.x;
    const int p0  = (blockIdx.x * BLK + tid) * VEC;   // even position

    int iv = img[0];
    float img_f = (iv > 0 && iv < 1000000) ? (float)iv : __int_as_float(iv);
    const float stride = img_f / (float)G;            // 8.0

    // Both positions share b, a, yy (G even, GG even)
    const int b    = p0 / (A * GG);
    int rem        = p0 - b * (A * GG);
    const int a    = rem / GG;
    const int sidx = rem - a * GG;
    const int yy   = sidx / G;
    const int xx0  = sidx - yy * G;

    const float* base = x + ((size_t)(b * (A * F) + a * F)) * GG + sidx;

    // 10 independent streaming LDG.64 (read-once, evict-first)
    float2 v[F];
#pragma unroll
    for (int f = 0; f < F; f++)
        v[f] = __ldcs((const float2*)(base + (size_t)f * GG));

    const float SXY = 1.05f;
    const float OFF = 0.025f;
    const float aw  = c_anchor_w[a];
    const float ah  = c_anchor_h[a];
    const float fy  = (float)yy;

    float* sp = s + tid * (VEC * F);
#pragma unroll
    for (int j = 0; j < VEC; j++) {
        float r0 = (fsigmoid(j ? v[0].y : v[0].x) * SXY - OFF + (float)(xx0 + j)) * stride;
        float r1 = (fsigmoid(j ? v[1].y : v[1].x) * SXY - OFF + fy) * stride;
        float r2 = __expf(j ? v[2].y : v[2].x) * aw;
        float r3 = __expf(j ? v[3].y : v[3].x) * ah;
        ((float4*)(sp + j * F))[0] = make_float4(r0, r1, r2, r3);
        float r4 = j ? v[4].y : v[4].x;
        float r5 = j ? v[5].y : v[5].x;
        float r6 = fsigmoid(j ? v[6].y : v[6].x);
        float r7 = fsigmoid(j ? v[7].y : v[7].x);
        ((float4*)(sp + j * F))[1] = make_float4(r4, r5, r6, r7);
        float r8 = fsigmoid(j ? v[8].y : v[8].x);
        float r9 = fsigmoid(j ? v[9].y : v[9].x);
        ((float2*)(sp + j * F))[4] = make_float2(r8, r9);
    }

    __syncthreads();

    // Block output slice: 512*10 = 5120 contiguous floats = 1280 float4.
    // 5 fully-coalesced streaming STG.128 per thread.
    float4* ob = (float4*)(out + (size_t)blockIdx.x * (POS_PER_BLK * F));
    const float4* sf = (const float4*)s;
#pragma unroll
    for (int jj = 0; jj < 5; jj++)
        __stcs(&ob[tid + jj * BLK], sf[tid + jj * BLK]);
}

extern "C" void kernel_launch(void* const* d_in, const int* in_sizes, int n_in,
                              void* d_out, int out_size)
{
    const float* x   = (const float*)d_in[0];
    const int*   img = (n_in >= 2) ? (const int*)d_in[1] : nullptr;
    float*       out = (float*)d_out;

    const int total = B * A * GG;             // 4,435,968
    const int grid  = total / POS_PER_BLK;    // 8664 exactly

    yolo_kernel<<<grid, BLK>>>(x, img, out);
}